// round 2
// baseline (speedup 1.0000x reference)
#include <cuda_runtime.h>
#include <math.h>
#include <float.h>

#define B_      2
#define N_KP    256
#define C_      256
#define HF_     64
#define WF_     64
#define ROI_    15
#define P2_     225
#define HID_    256
#define HEADS_  8
#define DH_     32
#define DEPTH_  3
#define FFN_    1024
#define NQ_     16
#define BN_     512          // B_*N_KP
#define MROWS_  8192         // BN_*NQ_
#define MMEM_   115200       // BN_*P2_
#define SPAD_   228
#define LN_EPS_ 1e-5f

// ---------------- scratch (static __device__ arrays; no allocation) ----------------
__device__ float g_imgT[(size_t)B_ * HF_ * WF_ * C_];     // (B,H,W,C)
__device__ float g_feat[(size_t)MMEM_ * C_];
__device__ float g_mem [(size_t)MMEM_ * C_];
__device__ float g_tgt [(size_t)MROWS_ * HID_];
__device__ float g_y   [(size_t)MROWS_ * HID_];
__device__ float g_qkv [(size_t)MROWS_ * 3 * HID_];
__device__ float g_ctx [(size_t)MROWS_ * HID_];
__device__ float g_qc  [(size_t)MROWS_ * HID_];
__device__ float g_u   [(size_t)BN_ * 128 * HID_];        // U, then reused for T
__device__ float g_s   [(size_t)BN_ * 128 * SPAD_];
__device__ float g_ffn [(size_t)MROWS_ * FFN_];
__device__ unsigned char g_valid[BN_];

// ---------------- mask decode (robust to uint8-bool or int32 storage) ----------------
__global__ void decode_mask(const unsigned char* __restrict__ m, unsigned char* __restrict__ out) {
    __shared__ int flag;
    if (threadIdx.x == 0) flag = 0;
    __syncthreads();
    int i = threadIdx.x;              // 512 threads
    unsigned char v8 = m[i];
    if ((i & 3) != 0 && v8 != 0) atomicOr(&flag, 1);
    __syncthreads();
    if (flag) out[i] = (v8 != 0);                           // 1-byte bool layout
    else      out[i] = (((const int*)m)[i] != 0);           // int32 layout
}

// ---------------- image transpose (B,C,H,W) -> (B,H,W,C) ----------------
__global__ void transpose_img(const float* __restrict__ img) {
    int x = blockIdx.x, y = blockIdx.y, b = blockIdx.z, c = threadIdx.x;
    g_imgT[(((size_t)b * HF_ + y) * WF_ + x) * C_ + c] =
        img[(((size_t)b * C_ + c) * HF_ + y) * WF_ + x];
}

// ---------------- ROI bilinear gather ----------------
__global__ __launch_bounds__(256) void roi_gather(const float* __restrict__ kp) {
    int p = blockIdx.x;           // 0..224
    int n = blockIdx.y;
    int b = blockIdx.z;
    int c = threadIdx.x;
    int iy = p / ROI_, ix = p % ROI_;
    float rc0 = rintf(kp[((size_t)b * N_KP + n) * 2 + 0]);   // half-even, matches jnp.round
    float rc1 = rintf(kp[((size_t)b * N_KP + n) * 2 + 1]);
    float gy = rc0 + (float)(iy - 7);
    float gx = rc1 + (float)(ix - 7);
    float gxn = __fdiv_rn(gx, 511.0f) * 2.0f - 1.0f;
    float gyn = __fdiv_rn(gy, 511.0f) * 2.0f - 1.0f;
    bool invalid = (gxn < -1.0f) || (gyn < -1.0f) || (gxn > 1.0f) || (gyn > 1.0f);
    float* dst = g_feat + ((size_t)((b * N_KP + n) * P2_ + p)) * C_;
    if (invalid) { dst[c] = 0.0f; return; }
    float x = ((gxn + 1.0f) * (float)WF_ - 1.0f) * 0.5f;
    float y = ((gyn + 1.0f) * (float)HF_ - 1.0f) * 0.5f;
    float x0f = floorf(x), y0f = floorf(y);
    float wx = x - x0f, wy = y - y0f;
    int x0 = (int)x0f, y0 = (int)y0f;
    int x1 = x0 + 1, y1 = y0 + 1;
    float w00 = (1.0f - wy) * (1.0f - wx);
    float w01 = (1.0f - wy) * wx;
    float w10 = wy * (1.0f - wx);
    float w11 = wy * wx;
    float acc = 0.0f;
    if (y0 >= 0 && y0 < HF_) {
        const float* rowp = g_imgT + ((size_t)(b * HF_ + y0) * WF_) * C_;
        if (x0 >= 0 && x0 < WF_) acc += w00 * rowp[(size_t)x0 * C_ + c];
        if (x1 >= 0 && x1 < WF_) acc += w01 * rowp[(size_t)x1 * C_ + c];
    }
    if (y1 >= 0 && y1 < HF_) {
        const float* rowp = g_imgT + ((size_t)(b * HF_ + y1) * WF_) * C_;
        if (x0 >= 0 && x0 < WF_) acc += w10 * rowp[(size_t)x0 * C_ + c];
        if (x1 >= 0 && x1 < WF_) acc += w11 * rowp[(size_t)x1 * C_ + c];
    }
    dst[c] = acc;
}

// ---------------- generic tiled GEMM: C = alpha * A @ op(B) [+ bias] [+ res] [relu] ----------------
// TB=true : B is (N,K) row-major (C = A @ B^T)   TB=false : B is (K,N) row-major
template<bool TB, bool HAS_BIAS, bool HAS_RES, bool RELU>
__global__ __launch_bounds__(256) void gemm_k(
    const float* __restrict__ A, const float* __restrict__ B,
    const float* __restrict__ bias, const float* __restrict__ Res,
    float* __restrict__ C,
    int M, int N, int K, int lda, int ldb, int ldc,
    long long sA, long long sB, long long sC, float alpha)
{
    long long z = blockIdx.z;
    A += z * sA; B += z * sB; C += z * sC;
    if (HAS_RES) Res += z * sC;
    __shared__ float As[16][68];
    __shared__ float Bs[16][68];
    int m0 = blockIdx.y * 64, n0 = blockIdx.x * 64;
    int t = threadIdx.x;
    int tx = t & 15, ty = t >> 4;
    float acc[4][4] = {};
    for (int k0 = 0; k0 < K; k0 += 16) {
#pragma unroll
        for (int i = 0; i < 4; i++) {
            int lin = t + i * 256;
            int mm = lin >> 4, kk = lin & 15;
            int gm = m0 + mm, gk = k0 + kk;
            As[kk][mm] = (gm < M && gk < K) ? A[(size_t)gm * lda + gk] : 0.0f;
        }
        if (TB) {
#pragma unroll
            for (int i = 0; i < 4; i++) {
                int lin = t + i * 256;
                int nn = lin >> 4, kk = lin & 15;
                int gn = n0 + nn, gk = k0 + kk;
                Bs[kk][nn] = (gn < N && gk < K) ? B[(size_t)gn * ldb + gk] : 0.0f;
            }
        } else {
#pragma unroll
            for (int i = 0; i < 4; i++) {
                int lin = t + i * 256;
                int kk = lin >> 6, nn = lin & 63;
                int gn = n0 + nn, gk = k0 + kk;
                Bs[kk][nn] = (gn < N && gk < K) ? B[(size_t)gk * ldb + gn] : 0.0f;
            }
        }
        __syncthreads();
#pragma unroll
        for (int kk = 0; kk < 16; kk++) {
            float4 a4 = *reinterpret_cast<const float4*>(&As[kk][ty * 4]);
            float4 b4 = *reinterpret_cast<const float4*>(&Bs[kk][tx * 4]);
            float av[4] = {a4.x, a4.y, a4.z, a4.w};
            float bv[4] = {b4.x, b4.y, b4.z, b4.w};
#pragma unroll
            for (int i = 0; i < 4; i++)
#pragma unroll
                for (int j = 0; j < 4; j++)
                    acc[i][j] += av[i] * bv[j];
        }
        __syncthreads();
    }
#pragma unroll
    for (int i = 0; i < 4; i++) {
        int gm = m0 + ty * 4 + i;
        if (gm >= M) continue;
#pragma unroll
        for (int j = 0; j < 4; j++) {
            int gn = n0 + tx * 4 + j;
            if (gn >= N) continue;
            float v = acc[i][j] * alpha;
            if (HAS_BIAS) v += bias[gn];
            if (HAS_RES)  v += Res[(size_t)gm * ldc + gn];
            if (RELU)     v = fmaxf(v, 0.0f);
            C[(size_t)gm * ldc + gn] = v;
        }
    }
}

// ---------------- tgt init: broadcast query_embed ----------------
__global__ void init_tgt(const float* __restrict__ qe) {
    size_t i = (size_t)blockIdx.x * 256 + threadIdx.x;   // 8192*256 total
    int c = (int)(i & 255);
    int m = (int)(i >> 8);
    int q = m & 15;
    g_tgt[i] = qe[q * HID_ + c];
}

// ---------------- self attention (16x16 per head, per sequence) ----------------
__global__ __launch_bounds__(256) void self_attn() {
    int bn = blockIdx.x;
    __shared__ float sq[NQ_][260];
    __shared__ float sk[NQ_][260];
    __shared__ float sa[HEADS_][NQ_][NQ_ + 1];
    int t = threadIdx.x;
    const float* base = g_qkv + (size_t)bn * NQ_ * 768;
    for (int i = t; i < NQ_ * HID_; i += 256) {
        int q = i >> 8, c = i & 255;
        sq[q][c] = base[q * 768 + c];
        sk[q][c] = base[q * 768 + 256 + c];
    }
    __syncthreads();
    const float scale = 0.17677669529663687f;   // 1/sqrt(32)
    for (int i = t; i < HEADS_ * NQ_ * NQ_; i += 256) {
        int h = i >> 8, q = (i >> 4) & 15, kk = i & 15;
        float acc = 0.0f;
#pragma unroll
        for (int d = 0; d < DH_; d++) acc += sq[q][h * DH_ + d] * sk[kk][h * DH_ + d];
        sa[h][q][kk] = acc * scale;
    }
    __syncthreads();
    if (t < HEADS_ * NQ_) {
        int h = t >> 4, q = t & 15;
        float m = -FLT_MAX;
#pragma unroll
        for (int kk = 0; kk < NQ_; kk++) m = fmaxf(m, sa[h][q][kk]);
        float s = 0.0f;
#pragma unroll
        for (int kk = 0; kk < NQ_; kk++) { float e = expf(sa[h][q][kk] - m); sa[h][q][kk] = e; s += e; }
        float inv = 1.0f / s;
#pragma unroll
        for (int kk = 0; kk < NQ_; kk++) sa[h][q][kk] *= inv;
    }
    __syncthreads();
    float* out = g_ctx + (size_t)bn * NQ_ * HID_;
    for (int i = t; i < NQ_ * HID_; i += 256) {
        int q = i >> 8, c = i & 255;
        int h = c >> 5;
        float acc = 0.0f;
#pragma unroll
        for (int kk = 0; kk < NQ_; kk++) acc += sa[h][q][kk] * base[kk * 768 + 512 + c];
        out[q * HID_ + c] = acc;
    }
}

// ---------------- cross-attn U = Q_h @ Wk_h (factored keys) ----------------
__global__ __launch_bounds__(256) void cross_u(const float* __restrict__ Wk) {
    int h = blockIdx.x;     // 8
    int bn = blockIdx.y;    // 512
    int c = threadIdx.x;    // 256
    __shared__ float sq[NQ_][DH_];
    for (int i = threadIdx.x; i < NQ_ * DH_; i += 256) {
        int q = i >> 5, d = i & 31;
        sq[q][d] = g_qc[((size_t)bn * NQ_ + q) * HID_ + h * DH_ + d];
    }
    __syncthreads();
    float acc[NQ_] = {};
#pragma unroll 4
    for (int d = 0; d < DH_; d++) {
        float w = Wk[(size_t)(h * DH_ + d) * HID_ + c];
#pragma unroll
        for (int q = 0; q < NQ_; q++) acc[q] += sq[q][d] * w;
    }
    float* dst = g_u + ((size_t)bn * 128 + h * NQ_) * HID_ + c;
#pragma unroll
    for (int q = 0; q < NQ_; q++) dst[(size_t)q * HID_] = acc[q];
}

// ---------------- masked softmax over 225 keys ----------------
__global__ __launch_bounds__(256) void softmax_cross() {
    int row = blockIdx.x * 8 + (threadIdx.x >> 5);   // 65536 rows: (bn*8+h)*16+q
    int lane = threadIdx.x & 31;
    int bn = row >> 7;
    bool v = g_valid[bn] != 0;
    float* s = g_s + (size_t)row * SPAD_;
    float vals[8];
    float m = -FLT_MAX;
#pragma unroll
    for (int i = 0; i < 8; i++) {
        int k = lane + i * 32;
        bool active = (k < P2_) && (v || k == 0);
        float x = active ? s[k] : -FLT_MAX;
        vals[i] = active ? x : -INFINITY;
        m = fmaxf(m, vals[i]);
    }
#pragma unroll
    for (int o = 16; o; o >>= 1) m = fmaxf(m, __shfl_xor_sync(0xffffffffu, m, o));
    float sum = 0.0f;
#pragma unroll
    for (int i = 0; i < 8; i++) {
        int k = lane + i * 32;
        bool active = (k < P2_) && (v || k == 0);
        float e = active ? expf(vals[i] - m) : 0.0f;
        vals[i] = e;
        sum += e;
    }
#pragma unroll
    for (int o = 16; o; o >>= 1) sum += __shfl_xor_sync(0xffffffffu, sum, o);
    float inv = 1.0f / sum;
#pragma unroll
    for (int i = 0; i < 8; i++) {
        int k = lane + i * 32;
        if (k < P2_) s[k] = vals[i] * inv;
    }
}

// ---------------- cross-attn output: ctx = T @ Wv_h^T + bv ----------------
__global__ __launch_bounds__(512) void cross_o(const float* __restrict__ Wv,
                                               const float* __restrict__ bv) {
    int h = blockIdx.x, bn = blockIdx.y;
    __shared__ float ws[DH_][HID_ + 1];
    int t = threadIdx.x;
    for (int i = t; i < DH_ * HID_; i += 512) {
        int d = i >> 8, c = i & 255;
        ws[d][c] = Wv[(size_t)(h * DH_ + d) * HID_ + c];
    }
    __syncthreads();
    int q = t >> 5, d = t & 31;
    const float* trow = g_u + ((size_t)bn * 128 + h * NQ_ + q) * HID_;
    float acc = 0.0f;
#pragma unroll 4
    for (int c = 0; c < HID_; c += 4) {
        float4 tv = *reinterpret_cast<const float4*>(trow + c);
        acc += tv.x * ws[d][c] + tv.y * ws[d][c + 1] + tv.z * ws[d][c + 2] + tv.w * ws[d][c + 3];
    }
    g_ctx[((size_t)bn * NQ_ + q) * HID_ + h * DH_ + d] = acc + bv[h * DH_ + d];
}

// ---------------- layernorm (warp per row of 256) ----------------
__global__ __launch_bounds__(256) void layernorm_k(const float* __restrict__ X,
                                                   const float* __restrict__ w,
                                                   const float* __restrict__ b,
                                                   float* __restrict__ Y) {
    int row = blockIdx.x * 8 + (threadIdx.x >> 5);
    int lane = threadIdx.x & 31;
    const float* x = X + (size_t)row * HID_;
    float v[8];
    float s = 0.0f;
#pragma unroll
    for (int i = 0; i < 8; i++) { v[i] = x[lane + i * 32]; s += v[i]; }
#pragma unroll
    for (int o = 16; o; o >>= 1) s += __shfl_xor_sync(0xffffffffu, s, o);
    float mu = s * (1.0f / 256.0f);
    float var = 0.0f;
#pragma unroll
    for (int i = 0; i < 8; i++) { float d = v[i] - mu; var += d * d; }
#pragma unroll
    for (int o = 16; o; o >>= 1) var += __shfl_xor_sync(0xffffffffu, var, o);
    var *= (1.0f / 256.0f);
    float r = rsqrtf(var + LN_EPS_);
    float* y = Y + (size_t)row * HID_;
#pragma unroll
    for (int i = 0; i < 8; i++) {
        int c = lane + i * 32;
        y[c] = (v[i] - mu) * r * w[c] + b[c];
    }
}

// ---------------- final head (HID -> 4) ----------------
__global__ __launch_bounds__(256) void final_out(const float* __restrict__ W,
                                                 const float* __restrict__ bias,
                                                 float* __restrict__ out) {
    int row = blockIdx.x * 8 + (threadIdx.x >> 5);
    int lane = threadIdx.x & 31;
    const float* x = g_tgt + (size_t)row * HID_;
    float acc[4] = {};
#pragma unroll
    for (int i = 0; i < 8; i++) {
        int c = lane + i * 32;
        float xv = x[c];
#pragma unroll
        for (int j = 0; j < 4; j++) acc[j] += xv * W[j * HID_ + c];
    }
#pragma unroll
    for (int j = 0; j < 4; j++)
#pragma unroll
        for (int o = 16; o; o >>= 1) acc[j] += __shfl_xor_sync(0xffffffffu, acc[j], o);
    if (lane < 4) out[(size_t)row * 4 + lane] = acc[lane] + bias[lane];
}

// ---------------- host ----------------
extern "C" void kernel_launch(void* const* d_in, const int* in_sizes, int n_in,
                              void* d_out, int out_size) {
    (void)in_sizes; (void)n_in; (void)out_size;
    const float* img         = (const float*)d_in[0];
    const float* kp          = (const float*)d_in[1];
    const unsigned char* msk = (const unsigned char*)d_in[2];
    const float* proj_w      = (const float*)d_in[3];
    const float* proj_b      = (const float*)d_in[4];
    const float* query_embed = (const float*)d_in[5];
    const float* self_qkv_w  = (const float*)d_in[6];
    const float* self_qkv_b  = (const float*)d_in[7];
    const float* self_out_w  = (const float*)d_in[8];
    const float* self_out_b  = (const float*)d_in[9];
    const float* cross_qkv_w = (const float*)d_in[10];
    const float* cross_qkv_b = (const float*)d_in[11];
    const float* cross_out_w = (const float*)d_in[12];
    const float* cross_out_b = (const float*)d_in[13];
    const float* ffn1_w      = (const float*)d_in[14];
    const float* ffn1_b      = (const float*)d_in[15];
    const float* ffn2_w      = (const float*)d_in[16];
    const float* ffn2_b      = (const float*)d_in[17];
    const float* ln1_w       = (const float*)d_in[18];
    const float* ln1_b       = (const float*)d_in[19];
    const float* ln2_w       = (const float*)d_in[20];
    const float* ln2_b       = (const float*)d_in[21];
    const float* ln3_w       = (const float*)d_in[22];
    const float* ln3_b       = (const float*)d_in[23];
    const float* out_w       = (const float*)d_in[24];
    const float* out_b       = (const float*)d_in[25];
    float* out = (float*)d_out;

    float *feat, *mem, *tgt, *y, *qkv, *ctx, *qc, *u, *s, *ffn;
    unsigned char* valid;
    cudaGetSymbolAddress((void**)&feat,  g_feat);
    cudaGetSymbolAddress((void**)&mem,   g_mem);
    cudaGetSymbolAddress((void**)&tgt,   g_tgt);
    cudaGetSymbolAddress((void**)&y,     g_y);
    cudaGetSymbolAddress((void**)&qkv,   g_qkv);
    cudaGetSymbolAddress((void**)&ctx,   g_ctx);
    cudaGetSymbolAddress((void**)&qc,    g_qc);
    cudaGetSymbolAddress((void**)&u,     g_u);
    cudaGetSymbolAddress((void**)&s,     g_s);
    cudaGetSymbolAddress((void**)&ffn,   g_ffn);
    cudaGetSymbolAddress((void**)&valid, g_valid);

    const float scale = 0.17677669529663687f;

    decode_mask<<<1, 512>>>(msk, valid);
    {
        dim3 g(WF_, HF_, B_);
        transpose_img<<<g, C_>>>(img);
    }
    {
        dim3 g(P2_, N_KP, B_);
        roi_gather<<<g, C_>>>(kp);
    }
    // mem = feat @ proj_w^T + proj_b
    gemm_k<true, true, false, false><<<dim3((HID_ + 63) / 64, (MMEM_ + 63) / 64, 1), 256>>>(
        feat, proj_w, proj_b, nullptr, mem, MMEM_, HID_, C_, C_, C_, HID_, 0, 0, 0, 1.0f);

    init_tgt<<<MROWS_, 256>>>(query_embed);

    for (int l = 0; l < DEPTH_; l++) {
        const float* sW  = self_qkv_w  + (size_t)l * 3 * HID_ * HID_;
        const float* sB  = self_qkv_b  + (size_t)l * 3 * HID_;
        const float* soW = self_out_w  + (size_t)l * HID_ * HID_;
        const float* soB = self_out_b  + (size_t)l * HID_;
        const float* cW  = cross_qkv_w + (size_t)l * 3 * HID_ * HID_;
        const float* cB  = cross_qkv_b + (size_t)l * 3 * HID_;
        const float* coW = cross_out_w + (size_t)l * HID_ * HID_;
        const float* coB = cross_out_b + (size_t)l * HID_;
        const float* f1W = ffn1_w + (size_t)l * FFN_ * HID_;
        const float* f1B = ffn1_b + (size_t)l * FFN_;
        const float* f2W = ffn2_w + (size_t)l * HID_ * FFN_;
        const float* f2B = ffn2_b + (size_t)l * HID_;

        // --- self attention ---
        gemm_k<true, true, false, false><<<dim3((3 * HID_ + 63) / 64, (MROWS_ + 63) / 64, 1), 256>>>(
            tgt, sW, sB, nullptr, qkv, MROWS_, 3 * HID_, HID_, HID_, HID_, 3 * HID_, 0, 0, 0, 1.0f);
        self_attn<<<BN_, 256>>>();
        gemm_k<true, true, true, false><<<dim3((HID_ + 63) / 64, (MROWS_ + 63) / 64, 1), 256>>>(
            ctx, soW, soB, tgt, y, MROWS_, HID_, HID_, HID_, HID_, HID_, 0, 0, 0, 1.0f);
        layernorm_k<<<MROWS_ / 8, 256>>>(y, ln1_w + l * HID_, ln1_b + l * HID_, tgt);

        // --- cross attention (factored K/V) ---
        gemm_k<true, true, false, false><<<dim3((HID_ + 63) / 64, (MROWS_ + 63) / 64, 1), 256>>>(
            tgt, cW, cB, nullptr, qc, MROWS_, HID_, HID_, HID_, HID_, HID_, 0, 0, 0, 1.0f);
        {
            dim3 g(HEADS_, BN_);
            cross_u<<<g, 256>>>(cW + (size_t)HID_ * HID_);
        }
        // S = scale * U @ mem^T   (batched over bn)
        gemm_k<true, false, false, false><<<dim3((P2_ + 63) / 64, 2, BN_), 256>>>(
            u, mem, nullptr, nullptr, s, 128, P2_, HID_, HID_, HID_, SPAD_,
            (long long)128 * HID_, (long long)P2_ * HID_, (long long)128 * SPAD_, scale);
        softmax_cross<<<(BN_ * 128) / 8, 256>>>();
        // T = A @ mem   (batched, NN)
        gemm_k<false, false, false, false><<<dim3((HID_ + 63) / 64, 2, BN_), 256>>>(
            s, mem, nullptr, nullptr, u, 128, HID_, P2_, SPAD_, HID_, HID_,
            (long long)128 * SPAD_, (long long)P2_ * HID_, (long long)128 * HID_, 1.0f);
        {
            dim3 g(HEADS_, BN_);
            cross_o<<<g, 512>>>(cW + (size_t)2 * HID_ * HID_, cB + 2 * HID_);
        }
        gemm_k<true, true, true, false><<<dim3((HID_ + 63) / 64, (MROWS_ + 63) / 64, 1), 256>>>(
            ctx, coW, coB, tgt, y, MROWS_, HID_, HID_, HID_, HID_, HID_, 0, 0, 0, 1.0f);
        layernorm_k<<<MROWS_ / 8, 256>>>(y, ln2_w + l * HID_, ln2_b + l * HID_, tgt);

        // --- FFN ---
        gemm_k<true, true, false, true><<<dim3((FFN_ + 63) / 64, (MROWS_ + 63) / 64, 1), 256>>>(
            tgt, f1W, f1B, nullptr, ffn, MROWS_, FFN_, HID_, HID_, HID_, FFN_, 0, 0, 0, 1.0f);
        gemm_k<true, true, true, false><<<dim3((HID_ + 63) / 64, (MROWS_ + 63) / 64, 1), 256>>>(
            ffn, f2W, f2B, tgt, y, MROWS_, HID_, FFN_, FFN_, FFN_, HID_, 0, 0, 0, 1.0f);
        layernorm_k<<<MROWS_ / 8, 256>>>(y, ln3_w + l * HID_, ln3_b + l * HID_, tgt);
    }

    final_out<<<MROWS_ / 8, 256>>>(out_w, out_b, out);
}

// round 3
// speedup vs baseline: 1.3656x; 1.3656x over previous
#include <cuda_runtime.h>
#include <math.h>
#include <float.h>
#include <stdint.h>

#define B_      2
#define N_KP    256
#define C_      256
#define HF_     64
#define WF_     64
#define ROI_    15
#define P2_     225
#define HID_    256
#define HEADS_  8
#define DH_     32
#define DEPTH_  3
#define FFN_    1024
#define NQ_     16
#define BN_     512          // B_*N_KP
#define MROWS_  8192         // BN_*NQ_
#define MMEM_   115200       // BN_*P2_
#define SPAD_   228
#define LN_EPS_ 1e-5f

// ---------------- scratch ----------------
__device__ float g_imgT[(size_t)B_ * HF_ * WF_ * C_];
__device__ float g_feat[(size_t)MMEM_ * C_];
__device__ float g_mem [(size_t)MMEM_ * C_];
__device__ float g_tgt [(size_t)MROWS_ * HID_];
__device__ float g_y   [(size_t)MROWS_ * HID_];
__device__ float g_qkv [(size_t)MROWS_ * 3 * HID_];
__device__ float g_ctx [(size_t)MROWS_ * HID_];
__device__ float g_qc  [(size_t)MROWS_ * HID_];
__device__ float g_u   [(size_t)BN_ * 128 * HID_];
__device__ float g_s   [(size_t)BN_ * 128 * SPAD_];
__device__ float g_ffn [(size_t)MROWS_ * FFN_];
__device__ unsigned char g_valid[BN_];

// ---------------- helpers ----------------
__device__ __forceinline__ uint32_t f2tf(float f) {
    uint32_t u;
    asm("cvt.rna.tf32.f32 %0, %1;" : "=r"(u) : "f"(f));
    return u;
}

__device__ __forceinline__ void mma_tf32(float* c, const uint32_t* a, const uint32_t* b) {
    asm volatile(
        "mma.sync.aligned.m16n8k8.row.col.f32.tf32.tf32.f32 "
        "{%0,%1,%2,%3}, {%4,%5,%6,%7}, {%8,%9}, {%0,%1,%2,%3};\n"
        : "+f"(c[0]), "+f"(c[1]), "+f"(c[2]), "+f"(c[3])
        : "r"(a[0]), "r"(a[1]), "r"(a[2]), "r"(a[3]), "r"(b[0]), "r"(b[1]));
}

// ---------------- mask decode ----------------
__global__ void decode_mask(const unsigned char* __restrict__ m, unsigned char* __restrict__ out) {
    __shared__ int flag;
    if (threadIdx.x == 0) flag = 0;
    __syncthreads();
    int i = threadIdx.x;
    unsigned char v8 = m[i];
    if ((i & 3) != 0 && v8 != 0) atomicOr(&flag, 1);
    __syncthreads();
    if (flag) out[i] = (v8 != 0);
    else      out[i] = (((const int*)m)[i] != 0);
}

// ---------------- image transpose (B,C,H,W) -> (B,H,W,C) ----------------
__global__ void transpose_img(const float* __restrict__ img) {
    int x = blockIdx.x, y = blockIdx.y, b = blockIdx.z, c = threadIdx.x;
    g_imgT[(((size_t)b * HF_ + y) * WF_ + x) * C_ + c] =
        img[(((size_t)b * C_ + c) * HF_ + y) * WF_ + x];
}

// ---------------- ROI bilinear gather ----------------
__global__ __launch_bounds__(256) void roi_gather(const float* __restrict__ kp) {
    int p = blockIdx.x, n = blockIdx.y, b = blockIdx.z, c = threadIdx.x;
    int iy = p / ROI_, ix = p % ROI_;
    float rc0 = rintf(kp[((size_t)b * N_KP + n) * 2 + 0]);
    float rc1 = rintf(kp[((size_t)b * N_KP + n) * 2 + 1]);
    float gy = rc0 + (float)(iy - 7);
    float gx = rc1 + (float)(ix - 7);
    float gxn = __fdiv_rn(gx, 511.0f) * 2.0f - 1.0f;
    float gyn = __fdiv_rn(gy, 511.0f) * 2.0f - 1.0f;
    bool invalid = (gxn < -1.0f) || (gyn < -1.0f) || (gxn > 1.0f) || (gyn > 1.0f);
    float* dst = g_feat + ((size_t)((b * N_KP + n) * P2_ + p)) * C_;
    if (invalid) { dst[c] = 0.0f; return; }
    float x = ((gxn + 1.0f) * (float)WF_ - 1.0f) * 0.5f;
    float y = ((gyn + 1.0f) * (float)HF_ - 1.0f) * 0.5f;
    float x0f = floorf(x), y0f = floorf(y);
    float wx = x - x0f, wy = y - y0f;
    int x0 = (int)x0f, y0 = (int)y0f;
    int x1 = x0 + 1, y1 = y0 + 1;
    float w00 = (1.0f - wy) * (1.0f - wx);
    float w01 = (1.0f - wy) * wx;
    float w10 = wy * (1.0f - wx);
    float w11 = wy * wx;
    float acc = 0.0f;
    if (y0 >= 0 && y0 < HF_) {
        const float* rowp = g_imgT + ((size_t)(b * HF_ + y0) * WF_) * C_;
        if (x0 >= 0 && x0 < WF_) acc += w00 * rowp[(size_t)x0 * C_ + c];
        if (x1 >= 0 && x1 < WF_) acc += w01 * rowp[(size_t)x1 * C_ + c];
    }
    if (y1 >= 0 && y1 < HF_) {
        const float* rowp = g_imgT + ((size_t)(b * HF_ + y1) * WF_) * C_;
        if (x0 >= 0 && x0 < WF_) acc += w10 * rowp[(size_t)x0 * C_ + c];
        if (x1 >= 0 && x1 < WF_) acc += w11 * rowp[(size_t)x1 * C_ + c];
    }
    dst[c] = acc;
}

// ================= tf32 tensor-core GEMM =================
// C = alpha * A @ op(B) [+ bias] [+ res] [relu]
// TB=true : B is (N,K) row-major.  TB=false : B is (K,N) row-major.
// Block tile 128x128, K-tile 16, 256 threads (8 warps as 2M x 4N, warp tile 64x32).
template<bool TB, bool HAS_BIAS, bool HAS_RES, bool RELU>
__global__ __launch_bounds__(256) void gemm_tc(
    const float* __restrict__ A, const float* __restrict__ B,
    const float* __restrict__ bias, const float* __restrict__ Res,
    float* __restrict__ C,
    int M, int N, int K, int lda, int ldb, int ldc,
    long long sA, long long sB, long long sC, float alpha)
{
    long long z = blockIdx.z;
    A += z * sA; B += z * sB; C += z * sC;
    if (HAS_RES) Res += z * sC;

    __shared__ uint32_t As[128][20];    // [m][k], stride 20 -> conflict-free frag reads
    __shared__ uint32_t Bs[16][136];    // [k][n], stride 136 -> conflict-free frag reads

    int m0 = blockIdx.y * 128, n0 = blockIdx.x * 128;
    int t = threadIdx.x;
    int wid = t >> 5, lane = t & 31;
    int warp_m = wid >> 2;        // 0..1
    int warp_n = wid & 3;         // 0..3
    int g = lane >> 2, tq = lane & 3;

    float acc[4][4][4];
#pragma unroll
    for (int i = 0; i < 4; i++)
#pragma unroll
        for (int j = 0; j < 4; j++)
#pragma unroll
            for (int r = 0; r < 4; r++) acc[i][j][r] = 0.0f;

    for (int k0 = 0; k0 < K; k0 += 16) {
        // ---- load A tile (128x16) ----
#pragma unroll
        for (int i = 0; i < 2; i++) {
            int m = (t >> 2) + i * 64;
            int kk = (t & 3) * 4;
            int gm = m0 + m, gk = k0 + kk;
            float4 v = make_float4(0.f, 0.f, 0.f, 0.f);
            if (gm < M) {
                if (gk + 3 < K) {
                    v = *reinterpret_cast<const float4*>(A + (size_t)gm * lda + gk);
                } else {
                    float* vv = &v.x;
#pragma unroll
                    for (int j = 0; j < 4; j++)
                        if (gk + j < K) vv[j] = A[(size_t)gm * lda + gk + j];
                }
            }
            As[m][kk + 0] = f2tf(v.x);
            As[m][kk + 1] = f2tf(v.y);
            As[m][kk + 2] = f2tf(v.z);
            As[m][kk + 3] = f2tf(v.w);
        }
        // ---- load B tile -> Bs[k][n] (16x128) ----
        if (TB) {
#pragma unroll
            for (int i = 0; i < 2; i++) {
                int n = (t >> 2) + i * 64;
                int kk = (t & 3) * 4;
                int gn = n0 + n, gk = k0 + kk;
                float4 v = make_float4(0.f, 0.f, 0.f, 0.f);
                if (gn < N) {
                    if (gk + 3 < K) {
                        v = *reinterpret_cast<const float4*>(B + (size_t)gn * ldb + gk);
                    } else {
                        float* vv = &v.x;
#pragma unroll
                        for (int j = 0; j < 4; j++)
                            if (gk + j < K) vv[j] = B[(size_t)gn * ldb + gk + j];
                    }
                }
                Bs[kk + 0][n] = f2tf(v.x);
                Bs[kk + 1][n] = f2tf(v.y);
                Bs[kk + 2][n] = f2tf(v.z);
                Bs[kk + 3][n] = f2tf(v.w);
            }
        } else {
            int kk = t >> 4;             // 0..15
            int n  = (t & 15) * 8;       // 0..120
            int gk = k0 + kk;
#pragma unroll
            for (int half = 0; half < 2; half++) {
                int nn = n + half * 4;
                int gn = n0 + nn;
                float4 v = make_float4(0.f, 0.f, 0.f, 0.f);
                if (gk < K) {
                    if (gn + 3 < N) {
                        v = *reinterpret_cast<const float4*>(B + (size_t)gk * ldb + gn);
                    } else {
                        float* vv = &v.x;
#pragma unroll
                        for (int j = 0; j < 4; j++)
                            if (gn + j < N) vv[j] = B[(size_t)gk * ldb + gn + j];
                    }
                }
                Bs[kk][nn + 0] = f2tf(v.x);
                Bs[kk][nn + 1] = f2tf(v.y);
                Bs[kk][nn + 2] = f2tf(v.z);
                Bs[kk][nn + 3] = f2tf(v.w);
            }
        }
        __syncthreads();

        // ---- compute: two k8 sub-steps ----
#pragma unroll
        for (int ks = 0; ks < 16; ks += 8) {
            uint32_t af[4][4];
#pragma unroll
            for (int mt = 0; mt < 4; mt++) {
                int mrow = warp_m * 64 + mt * 16;
                af[mt][0] = As[mrow + g][ks + tq];
                af[mt][1] = As[mrow + g + 8][ks + tq];
                af[mt][2] = As[mrow + g][ks + tq + 4];
                af[mt][3] = As[mrow + g + 8][ks + tq + 4];
            }
            uint32_t bf[4][2];
#pragma unroll
            for (int nt = 0; nt < 4; nt++) {
                int ncol = warp_n * 32 + nt * 8 + g;
                bf[nt][0] = Bs[ks + tq][ncol];
                bf[nt][1] = Bs[ks + tq + 4][ncol];
            }
#pragma unroll
            for (int mt = 0; mt < 4; mt++)
#pragma unroll
                for (int nt = 0; nt < 4; nt++)
                    mma_tf32(acc[mt][nt], af[mt], bf[nt]);
        }
        __syncthreads();
    }

    // ---- epilogue ----
#pragma unroll
    for (int mt = 0; mt < 4; mt++) {
        int row0 = m0 + warp_m * 64 + mt * 16 + g;
#pragma unroll
        for (int nt = 0; nt < 4; nt++) {
            int col = n0 + warp_n * 32 + nt * 8 + tq * 2;
#pragma unroll
            for (int half = 0; half < 2; half++) {
                int row = row0 + half * 8;
                if (row >= M) continue;
                float v0 = acc[mt][nt][half * 2 + 0] * alpha;
                float v1 = acc[mt][nt][half * 2 + 1] * alpha;
                if (col < N) {
                    float v = v0;
                    if (HAS_BIAS) v += bias[col];
                    if (HAS_RES)  v += Res[(size_t)row * ldc + col];
                    if (RELU)     v = fmaxf(v, 0.0f);
                    C[(size_t)row * ldc + col] = v;
                }
                if (col + 1 < N) {
                    float v = v1;
                    if (HAS_BIAS) v += bias[col + 1];
                    if (HAS_RES)  v += Res[(size_t)row * ldc + col + 1];
                    if (RELU)     v = fmaxf(v, 0.0f);
                    C[(size_t)row * ldc + col + 1] = v;
                }
            }
        }
    }
}

// ---------------- tgt init ----------------
__global__ void init_tgt(const float* __restrict__ qe) {
    size_t i = (size_t)blockIdx.x * 256 + threadIdx.x;
    int c = (int)(i & 255);
    int m = (int)(i >> 8);
    int q = m & 15;
    g_tgt[i] = qe[q * HID_ + c];
}

// ---------------- self attention ----------------
__global__ __launch_bounds__(256) void self_attn() {
    int bn = blockIdx.x;
    __shared__ float sq[NQ_][260];
    __shared__ float sk[NQ_][260];
    __shared__ float sa[HEADS_][NQ_][NQ_ + 1];
    int t = threadIdx.x;
    const float* base = g_qkv + (size_t)bn * NQ_ * 768;
    for (int i = t; i < NQ_ * HID_; i += 256) {
        int q = i >> 8, c = i & 255;
        sq[q][c] = base[q * 768 + c];
        sk[q][c] = base[q * 768 + 256 + c];
    }
    __syncthreads();
    const float scale = 0.17677669529663687f;
    for (int i = t; i < HEADS_ * NQ_ * NQ_; i += 256) {
        int h = i >> 8, q = (i >> 4) & 15, kk = i & 15;
        float acc = 0.0f;
#pragma unroll
        for (int d = 0; d < DH_; d++) acc += sq[q][h * DH_ + d] * sk[kk][h * DH_ + d];
        sa[h][q][kk] = acc * scale;
    }
    __syncthreads();
    if (t < HEADS_ * NQ_) {
        int h = t >> 4, q = t & 15;
        float m = -FLT_MAX;
#pragma unroll
        for (int kk = 0; kk < NQ_; kk++) m = fmaxf(m, sa[h][q][kk]);
        float s = 0.0f;
#pragma unroll
        for (int kk = 0; kk < NQ_; kk++) { float e = expf(sa[h][q][kk] - m); sa[h][q][kk] = e; s += e; }
        float inv = 1.0f / s;
#pragma unroll
        for (int kk = 0; kk < NQ_; kk++) sa[h][q][kk] *= inv;
    }
    __syncthreads();
    float* out = g_ctx + (size_t)bn * NQ_ * HID_;
    for (int i = t; i < NQ_ * HID_; i += 256) {
        int q = i >> 8, c = i & 255;
        int h = c >> 5;
        float acc = 0.0f;
#pragma unroll
        for (int kk = 0; kk < NQ_; kk++) acc += sa[h][q][kk] * base[kk * 768 + 512 + c];
        out[q * HID_ + c] = acc;
    }
}

// ---------------- cross-attn U = Q_h @ Wk_h ----------------
__global__ __launch_bounds__(256) void cross_u(const float* __restrict__ Wk) {
    int h = blockIdx.x, bn = blockIdx.y;
    int c = threadIdx.x;
    __shared__ float sq[NQ_][DH_];
    for (int i = threadIdx.x; i < NQ_ * DH_; i += 256) {
        int q = i >> 5, d = i & 31;
        sq[q][d] = g_qc[((size_t)bn * NQ_ + q) * HID_ + h * DH_ + d];
    }
    __syncthreads();
    float acc[NQ_] = {};
#pragma unroll 4
    for (int d = 0; d < DH_; d++) {
        float w = Wk[(size_t)(h * DH_ + d) * HID_ + c];
#pragma unroll
        for (int q = 0; q < NQ_; q++) acc[q] += sq[q][d] * w;
    }
    float* dst = g_u + ((size_t)bn * 128 + h * NQ_) * HID_ + c;
#pragma unroll
    for (int q = 0; q < NQ_; q++) dst[(size_t)q * HID_] = acc[q];
}

// ---------------- masked softmax over 225 keys ----------------
__global__ __launch_bounds__(256) void softmax_cross() {
    int row = blockIdx.x * 8 + (threadIdx.x >> 5);
    int lane = threadIdx.x & 31;
    int bn = row >> 7;
    bool v = g_valid[bn] != 0;
    float* s = g_s + (size_t)row * SPAD_;
    float vals[8];
    float m = -FLT_MAX;
#pragma unroll
    for (int i = 0; i < 8; i++) {
        int k = lane + i * 32;
        bool active = (k < P2_) && (v || k == 0);
        float x = active ? s[k] : -FLT_MAX;
        vals[i] = active ? x : -INFINITY;
        m = fmaxf(m, vals[i]);
    }
#pragma unroll
    for (int o = 16; o; o >>= 1) m = fmaxf(m, __shfl_xor_sync(0xffffffffu, m, o));
    float sum = 0.0f;
#pragma unroll
    for (int i = 0; i < 8; i++) {
        int k = lane + i * 32;
        bool active = (k < P2_) && (v || k == 0);
        float e = active ? expf(vals[i] - m) : 0.0f;
        vals[i] = e;
        sum += e;
    }
#pragma unroll
    for (int o = 16; o; o >>= 1) sum += __shfl_xor_sync(0xffffffffu, sum, o);
    float inv = 1.0f / sum;
#pragma unroll
    for (int i = 0; i < 8; i++) {
        int k = lane + i * 32;
        if (k < P2_) s[k] = vals[i] * inv;
    }
}

// ---------------- cross-attn output: ctx = T @ Wv_h^T + bv ----------------
__global__ __launch_bounds__(512) void cross_o(const float* __restrict__ Wv,
                                               const float* __restrict__ bv) {
    int h = blockIdx.x, bn = blockIdx.y;
    __shared__ float ws[DH_][HID_ + 1];
    int t = threadIdx.x;
    for (int i = t; i < DH_ * HID_; i += 512) {
        int d = i >> 8, c = i & 255;
        ws[d][c] = Wv[(size_t)(h * DH_ + d) * HID_ + c];
    }
    __syncthreads();
    int q = t >> 5, d = t & 31;
    const float* trow = g_u + ((size_t)bn * 128 + h * NQ_ + q) * HID_;
    float acc = 0.0f;
#pragma unroll 4
    for (int c = 0; c < HID_; c += 4) {
        float4 tv = *reinterpret_cast<const float4*>(trow + c);
        acc += tv.x * ws[d][c] + tv.y * ws[d][c + 1] + tv.z * ws[d][c + 2] + tv.w * ws[d][c + 3];
    }
    g_ctx[((size_t)bn * NQ_ + q) * HID_ + h * DH_ + d] = acc + bv[h * DH_ + d];
}

// ---------------- layernorm ----------------
__global__ __launch_bounds__(256) void layernorm_k(const float* __restrict__ X,
                                                   const float* __restrict__ w,
                                                   const float* __restrict__ b,
                                                   float* __restrict__ Y) {
    int row = blockIdx.x * 8 + (threadIdx.x >> 5);
    int lane = threadIdx.x & 31;
    const float* x = X + (size_t)row * HID_;
    float v[8];
    float s = 0.0f;
#pragma unroll
    for (int i = 0; i < 8; i++) { v[i] = x[lane + i * 32]; s += v[i]; }
#pragma unroll
    for (int o = 16; o; o >>= 1) s += __shfl_xor_sync(0xffffffffu, s, o);
    float mu = s * (1.0f / 256.0f);
    float var = 0.0f;
#pragma unroll
    for (int i = 0; i < 8; i++) { float d = v[i] - mu; var += d * d; }
#pragma unroll
    for (int o = 16; o; o >>= 1) var += __shfl_xor_sync(0xffffffffu, var, o);
    var *= (1.0f / 256.0f);
    float r = rsqrtf(var + LN_EPS_);
    float* y = Y + (size_t)row * HID_;
#pragma unroll
    for (int i = 0; i < 8; i++) {
        int c = lane + i * 32;
        y[c] = (v[i] - mu) * r * w[c] + b[c];
    }
}

// ---------------- final head ----------------
__global__ __launch_bounds__(256) void final_out(const float* __restrict__ W,
                                                 const float* __restrict__ bias,
                                                 float* __restrict__ out) {
    int row = blockIdx.x * 8 + (threadIdx.x >> 5);
    int lane = threadIdx.x & 31;
    const float* x = g_tgt + (size_t)row * HID_;
    float acc[4] = {};
#pragma unroll
    for (int i = 0; i < 8; i++) {
        int c = lane + i * 32;
        float xv = x[c];
#pragma unroll
        for (int j = 0; j < 4; j++) acc[j] += xv * W[j * HID_ + c];
    }
#pragma unroll
    for (int j = 0; j < 4; j++)
#pragma unroll
        for (int o = 16; o; o >>= 1) acc[j] += __shfl_xor_sync(0xffffffffu, acc[j], o);
    if (lane < 4) out[(size_t)row * 4 + lane] = acc[lane] + bias[lane];
}

// ---------------- host ----------------
extern "C" void kernel_launch(void* const* d_in, const int* in_sizes, int n_in,
                              void* d_out, int out_size) {
    (void)in_sizes; (void)n_in; (void)out_size;
    const float* img         = (const float*)d_in[0];
    const float* kp          = (const float*)d_in[1];
    const unsigned char* msk = (const unsigned char*)d_in[2];
    const float* proj_w      = (const float*)d_in[3];
    const float* proj_b      = (const float*)d_in[4];
    const float* query_embed = (const float*)d_in[5];
    const float* self_qkv_w  = (const float*)d_in[6];
    const float* self_qkv_b  = (const float*)d_in[7];
    const float* self_out_w  = (const float*)d_in[8];
    const float* self_out_b  = (const float*)d_in[9];
    const float* cross_qkv_w = (const float*)d_in[10];
    const float* cross_qkv_b = (const float*)d_in[11];
    const float* cross_out_w = (const float*)d_in[12];
    const float* cross_out_b = (const float*)d_in[13];
    const float* ffn1_w      = (const float*)d_in[14];
    const float* ffn1_b      = (const float*)d_in[15];
    const float* ffn2_w      = (const float*)d_in[16];
    const float* ffn2_b      = (const float*)d_in[17];
    const float* ln1_w       = (const float*)d_in[18];
    const float* ln1_b       = (const float*)d_in[19];
    const float* ln2_w       = (const float*)d_in[20];
    const float* ln2_b       = (const float*)d_in[21];
    const float* ln3_w       = (const float*)d_in[22];
    const float* ln3_b       = (const float*)d_in[23];
    const float* out_w       = (const float*)d_in[24];
    const float* out_b       = (const float*)d_in[25];
    float* out = (float*)d_out;

    float *feat, *mem, *tgt, *y, *qkv, *ctx, *qc, *u, *s, *ffn;
    unsigned char* valid;
    cudaGetSymbolAddress((void**)&feat,  g_feat);
    cudaGetSymbolAddress((void**)&mem,   g_mem);
    cudaGetSymbolAddress((void**)&tgt,   g_tgt);
    cudaGetSymbolAddress((void**)&y,     g_y);
    cudaGetSymbolAddress((void**)&qkv,   g_qkv);
    cudaGetSymbolAddress((void**)&ctx,   g_ctx);
    cudaGetSymbolAddress((void**)&qc,    g_qc);
    cudaGetSymbolAddress((void**)&u,     g_u);
    cudaGetSymbolAddress((void**)&s,     g_s);
    cudaGetSymbolAddress((void**)&ffn,   g_ffn);
    cudaGetSymbolAddress((void**)&valid, g_valid);

    const float scale = 0.17677669529663687f;

    decode_mask<<<1, 512>>>(msk, valid);
    { dim3 g(WF_, HF_, B_); transpose_img<<<g, C_>>>(img); }
    { dim3 g(P2_, N_KP, B_); roi_gather<<<g, C_>>>(kp); }

    // mem = feat @ proj_w^T + proj_b
    gemm_tc<true, true, false, false><<<dim3(2, 900, 1), 256>>>(
        feat, proj_w, proj_b, nullptr, mem, MMEM_, HID_, C_, C_, C_, HID_, 0, 0, 0, 1.0f);

    init_tgt<<<MROWS_, 256>>>(query_embed);

    for (int l = 0; l < DEPTH_; l++) {
        const float* sW  = self_qkv_w  + (size_t)l * 3 * HID_ * HID_;
        const float* sB  = self_qkv_b  + (size_t)l * 3 * HID_;
        const float* soW = self_out_w  + (size_t)l * HID_ * HID_;
        const float* soB = self_out_b  + (size_t)l * HID_;
        const float* cW  = cross_qkv_w + (size_t)l * 3 * HID_ * HID_;
        const float* cB  = cross_qkv_b + (size_t)l * 3 * HID_;
        const float* coW = cross_out_w + (size_t)l * HID_ * HID_;
        const float* coB = cross_out_b + (size_t)l * HID_;
        const float* f1W = ffn1_w + (size_t)l * FFN_ * HID_;
        const float* f1B = ffn1_b + (size_t)l * FFN_;
        const float* f2W = ffn2_w + (size_t)l * HID_ * FFN_;
        const float* f2B = ffn2_b + (size_t)l * FFN_ * 0 + (size_t)l * HID_;

        // --- self attention ---
        gemm_tc<true, true, false, false><<<dim3(6, 64, 1), 256>>>(
            tgt, sW, sB, nullptr, qkv, MROWS_, 3 * HID_, HID_, HID_, HID_, 3 * HID_, 0, 0, 0, 1.0f);
        self_attn<<<BN_, 256>>>();
        gemm_tc<true, true, true, false><<<dim3(2, 64, 1), 256>>>(
            ctx, soW, soB, tgt, y, MROWS_, HID_, HID_, HID_, HID_, HID_, 0, 0, 0, 1.0f);
        layernorm_k<<<MROWS_ / 8, 256>>>(y, ln1_w + l * HID_, ln1_b + l * HID_, tgt);

        // --- cross attention (factored K/V) ---
        gemm_tc<true, true, false, false><<<dim3(2, 64, 1), 256>>>(
            tgt, cW, cB, nullptr, qc, MROWS_, HID_, HID_, HID_, HID_, HID_, 0, 0, 0, 1.0f);
        { dim3 g(HEADS_, BN_); cross_u<<<g, 256>>>(cW + (size_t)HID_ * HID_); }
        // S = scale * U @ mem^T   (batched over bn)
        gemm_tc<true, false, false, false><<<dim3(2, 1, BN_), 256>>>(
            u, mem, nullptr, nullptr, s, 128, P2_, HID_, HID_, HID_, SPAD_,
            (long long)128 * HID_, (long long)P2_ * HID_, (long long)128 * SPAD_, scale);
        softmax_cross<<<(BN_ * 128) / 8, 256>>>();
        // T = A @ mem   (batched, NN)
        gemm_tc<false, false, false, false><<<dim3(2, 1, BN_), 256>>>(
            s, mem, nullptr, nullptr, u, 128, HID_, P2_, SPAD_, HID_, HID_,
            (long long)128 * SPAD_, (long long)P2_ * HID_, (long long)128 * HID_, 1.0f);
        { dim3 g(HEADS_, BN_); cross_o<<<g, 512>>>(cW + (size_t)2 * HID_ * HID_, cB + 2 * HID_); }
        gemm_tc<true, true, true, false><<<dim3(2, 64, 1), 256>>>(
            ctx, coW, coB, tgt, y, MROWS_, HID_, HID_, HID_, HID_, HID_, 0, 0, 0, 1.0f);
        layernorm_k<<<MROWS_ / 8, 256>>>(y, ln2_w + l * HID_, ln2_b + l * HID_, tgt);

        // --- FFN ---
        gemm_tc<true, true, false, true><<<dim3(8, 64, 1), 256>>>(
            tgt, f1W, f1B, nullptr, ffn, MROWS_, FFN_, HID_, HID_, HID_, FFN_, 0, 0, 0, 1.0f);
        gemm_tc<true, true, true, false><<<dim3(2, 64, 1), 256>>>(
            ffn, f2W, f2B, tgt, y, MROWS_, HID_, FFN_, FFN_, FFN_, HID_, 0, 0, 0, 1.0f);
        layernorm_k<<<MROWS_ / 8, 256>>>(y, ln3_w + l * HID_, ln3_b + l * HID_, tgt);
    }

    final_out<<<MROWS_ / 8, 256>>>(out_w, out_b, out);
}

// round 4
// speedup vs baseline: 2.1581x; 1.5804x over previous
#include <cuda_runtime.h>
#include <math.h>
#include <float.h>
#include <stdint.h>

#define B_      2
#define N_KP    256
#define C_      256
#define HF_     64
#define WF_     64
#define ROI_    15
#define P2_     225
#define HID_    256
#define HEADS_  8
#define DH_     32
#define DEPTH_  3
#define FFN_    1024
#define NQ_     16
#define BN_     512          // B_*N_KP
#define MROWS_  8192         // BN_*NQ_
#define MMEM_   115200       // BN_*P2_
#define SPAD_   240          // padded S row; cols 225..239 zeroed by softmax
#define LN_EPS_ 1e-5f

// ---------------- scratch ----------------
__device__ float g_imgT[(size_t)B_ * HF_ * WF_ * C_];
__device__ float g_feat[(size_t)MMEM_ * C_];
__device__ float g_mem [(size_t)MMEM_ * C_];
__device__ float g_tgt [(size_t)MROWS_ * HID_];
__device__ float g_y   [(size_t)MROWS_ * HID_];
__device__ float g_qkv [(size_t)MROWS_ * 3 * HID_];
__device__ float g_ctx [(size_t)MROWS_ * HID_];
__device__ float g_qc  [(size_t)MROWS_ * HID_];
__device__ float g_u   [(size_t)BN_ * 128 * HID_];
__device__ float g_s   [(size_t)BN_ * 128 * SPAD_];
__device__ float g_ffn [(size_t)MROWS_ * FFN_];
__device__ unsigned char g_valid[BN_];

// ---------------- helpers ----------------
__device__ __forceinline__ uint32_t f2tf(float f) {
    uint32_t u;
    asm("cvt.rna.tf32.f32 %0, %1;" : "=r"(u) : "f"(f));
    return u;
}

__device__ __forceinline__ void mma_tf32(float* c, const uint32_t* a, const uint32_t* b) {
    asm volatile(
        "mma.sync.aligned.m16n8k8.row.col.f32.tf32.tf32.f32 "
        "{%0,%1,%2,%3}, {%4,%5,%6,%7}, {%8,%9}, {%0,%1,%2,%3};\n"
        : "+f"(c[0]), "+f"(c[1]), "+f"(c[2]), "+f"(c[3])
        : "r"(a[0]), "r"(a[1]), "r"(a[2]), "r"(a[3]), "r"(b[0]), "r"(b[1]));
}

__device__ __forceinline__ void cpa16(void* smem_ptr, const void* gptr, bool pred) {
    uint32_t sa = (uint32_t)__cvta_generic_to_shared(smem_ptr);
    int sz = pred ? 16 : 0;
    asm volatile("cp.async.cg.shared.global [%0], [%1], 16, %2;\n"
                 :: "r"(sa), "l"(gptr), "r"(sz));
}
#define CPA_COMMIT() asm volatile("cp.async.commit_group;\n")
#define CPA_WAIT(n)  asm volatile("cp.async.wait_group %0;\n" :: "n"(n))

// ---------------- mask decode ----------------
__global__ void decode_mask(const unsigned char* __restrict__ m, unsigned char* __restrict__ out) {
    __shared__ int flag;
    if (threadIdx.x == 0) flag = 0;
    __syncthreads();
    int i = threadIdx.x;
    unsigned char v8 = m[i];
    if ((i & 3) != 0 && v8 != 0) atomicOr(&flag, 1);
    __syncthreads();
    if (flag) out[i] = (v8 != 0);
    else      out[i] = (((const int*)m)[i] != 0);
}

// ---------------- image transpose (B,C,H,W) -> (B,H,W,C) ----------------
__global__ void transpose_img(const float* __restrict__ img) {
    int x = blockIdx.x, y = blockIdx.y, b = blockIdx.z, c = threadIdx.x;
    g_imgT[(((size_t)b * HF_ + y) * WF_ + x) * C_ + c] =
        img[(((size_t)b * C_ + c) * HF_ + y) * WF_ + x];
}

// ---------------- ROI bilinear gather ----------------
__global__ __launch_bounds__(256) void roi_gather(const float* __restrict__ kp) {
    int p = blockIdx.x, n = blockIdx.y, b = blockIdx.z, c = threadIdx.x;
    int iy = p / ROI_, ix = p % ROI_;
    float rc0 = rintf(kp[((size_t)b * N_KP + n) * 2 + 0]);
    float rc1 = rintf(kp[((size_t)b * N_KP + n) * 2 + 1]);
    float gy = rc0 + (float)(iy - 7);
    float gx = rc1 + (float)(ix - 7);
    float gxn = __fdiv_rn(gx, 511.0f) * 2.0f - 1.0f;
    float gyn = __fdiv_rn(gy, 511.0f) * 2.0f - 1.0f;
    bool invalid = (gxn < -1.0f) || (gyn < -1.0f) || (gxn > 1.0f) || (gyn > 1.0f);
    float* dst = g_feat + ((size_t)((b * N_KP + n) * P2_ + p)) * C_;
    if (invalid) { dst[c] = 0.0f; return; }
    float x = ((gxn + 1.0f) * (float)WF_ - 1.0f) * 0.5f;
    float y = ((gyn + 1.0f) * (float)HF_ - 1.0f) * 0.5f;
    float x0f = floorf(x), y0f = floorf(y);
    float wx = x - x0f, wy = y - y0f;
    int x0 = (int)x0f, y0 = (int)y0f;
    int x1 = x0 + 1, y1 = y0 + 1;
    float w00 = (1.0f - wy) * (1.0f - wx);
    float w01 = (1.0f - wy) * wx;
    float w10 = wy * (1.0f - wx);
    float w11 = wy * wx;
    float acc = 0.0f;
    if (y0 >= 0 && y0 < HF_) {
        const float* rowp = g_imgT + ((size_t)(b * HF_ + y0) * WF_) * C_;
        if (x0 >= 0 && x0 < WF_) acc += w00 * rowp[(size_t)x0 * C_ + c];
        if (x1 >= 0 && x1 < WF_) acc += w01 * rowp[(size_t)x1 * C_ + c];
    }
    if (y1 >= 0 && y1 < HF_) {
        const float* rowp = g_imgT + ((size_t)(b * HF_ + y1) * WF_) * C_;
        if (x0 >= 0 && x0 < WF_) acc += w10 * rowp[(size_t)x0 * C_ + c];
        if (x1 >= 0 && x1 < WF_) acc += w11 * rowp[(size_t)x1 * C_ + c];
    }
    dst[c] = acc;
}

// ================= tf32 tensor-core GEMM, cp.async double-buffered =================
// C = alpha * A @ op(B) [+ bias] [+ res] [relu]
// TB=true : B is (N,K) row-major.  TB=false : B is (K,N) row-major.
// Block 128x128, K-tile 16, 256 threads (8 warps 2Mx4N, warp tile 64x32).
// Assumptions: lda rows readable in 16B chunks for any k-tile (K mult of 16, or
// A padded+zeroed to the next 16 as with g_s/SPAD_). N-boundary handled by
// cp.async zero-fill (TB) or exact N (NT). NT path: gk>=K chunks zero-filled.
template<bool TB, bool HAS_BIAS, bool HAS_RES, bool RELU>
__global__ __launch_bounds__(256, 2) void gemm_tc(
    const float* __restrict__ A, const float* __restrict__ B,
    const float* __restrict__ bias, const float* __restrict__ Res,
    float* __restrict__ C,
    int M, int N, int K, int lda, int ldb, int ldc,
    long long sA, long long sB, long long sC, float alpha)
{
    long long z = blockIdx.z;
    A += z * sA; B += z * sB; C += z * sC;
    if (HAS_RES) Res += z * sC;

    __shared__ float As[2][128][20];
    __shared__ float Bs[2][16][136];

    int m0 = blockIdx.y * 128, n0 = blockIdx.x * 128;
    int t = threadIdx.x;
    int wid = t >> 5, lane = t & 31;
    int warp_m = wid >> 2;
    int warp_n = wid & 3;
    int g = lane >> 2, tq = lane & 3;

    // per-thread load geometry (fixed across tiles)
    int a_m0 = (t >> 2);            // + i*64
    int a_k  = (t & 3) * 4;
    int nt_k = t >> 4;              // NT: B row within tile
    int nt_n = (t & 15) * 8;        // NT: B col base (two float4 halves)

    float acc[4][4][4];
#pragma unroll
    for (int i = 0; i < 4; i++)
#pragma unroll
        for (int j = 0; j < 4; j++)
#pragma unroll
            for (int r = 0; r < 4; r++) acc[i][j][r] = 0.0f;

    int KT = (K + 15) >> 4;

    // ---- tile loader ----
    auto load_tile = [&](int st, int k0) {
#pragma unroll
        for (int i = 0; i < 2; i++) {
            int m = a_m0 + i * 64;
            int gm = m0 + m, gk = k0 + a_k;
            cpa16(&As[st][m][a_k], A + (size_t)gm * lda + gk, gm < M);
        }
        if (TB) {
#pragma unroll
            for (int i = 0; i < 2; i++) {
                int n = a_m0 + i * 64;
                int gn = n0 + n, gk = k0 + a_k;
                // store B transposed later? no: keep [k][n] layout via 4 scalar? must copy 16B along k.
                // Bs is [k][n]; a 16B chunk along k cannot target [k][n] directly.
                // Instead stage TB loads into Bs as [n-major] requires transpose; so for TB we
                // copy into a k-major staging row: use Bs[st] viewed as [128][17]? -> handled below.
                (void)gn; (void)gk; (void)n;
            }
        }
    };
    (void)load_tile;

    // NOTE: TB B tiles need a transpose between gmem (n-major rows of k) and Bs[k][n].
    // We stage them in n-major layout BsT[st][n][k] (128x20 like As) and read fragments from it.
    __shared__ float BsT[2][128][20];

    auto load_tile2 = [&](int st, int k0) {
#pragma unroll
        for (int i = 0; i < 2; i++) {
            int m = a_m0 + i * 64;
            int gm = m0 + m, gk = k0 + a_k;
            cpa16(&As[st][m][a_k], A + (size_t)gm * lda + gk, gm < M);
        }
        if (TB) {
#pragma unroll
            for (int i = 0; i < 2; i++) {
                int n = a_m0 + i * 64;
                int gn = n0 + n, gk = k0 + a_k;
                cpa16(&BsT[st][n][a_k], B + (size_t)gn * ldb + gk, gn < N);
            }
        } else {
            int gk = k0 + nt_k;
#pragma unroll
            for (int half = 0; half < 2; half++) {
                int nn = nt_n + half * 4;
                int gn = n0 + nn;
                cpa16(&Bs[st][nt_k][nn], B + (size_t)gk * ldb + gn, gk < K);
            }
        }
    };

    load_tile2(0, 0);
    CPA_COMMIT();

    for (int kt = 0; kt < KT; kt++) {
        if (kt + 1 < KT) {
            load_tile2((kt + 1) & 1, (kt + 1) * 16);
            CPA_COMMIT();
            CPA_WAIT(1);
        } else {
            CPA_WAIT(0);
        }
        __syncthreads();

        int st = kt & 1;
#pragma unroll
        for (int ks = 0; ks < 16; ks += 8) {
            uint32_t af[4][4];
#pragma unroll
            for (int mt = 0; mt < 4; mt++) {
                int mrow = warp_m * 64 + mt * 16;
                af[mt][0] = f2tf(As[st][mrow + g][ks + tq]);
                af[mt][1] = f2tf(As[st][mrow + g + 8][ks + tq]);
                af[mt][2] = f2tf(As[st][mrow + g][ks + tq + 4]);
                af[mt][3] = f2tf(As[st][mrow + g + 8][ks + tq + 4]);
            }
            uint32_t bf[4][2];
#pragma unroll
            for (int nt = 0; nt < 4; nt++) {
                int ncol = warp_n * 32 + nt * 8 + g;
                if (TB) {
                    bf[nt][0] = f2tf(BsT[st][ncol][ks + tq]);
                    bf[nt][1] = f2tf(BsT[st][ncol][ks + tq + 4]);
                } else {
                    bf[nt][0] = f2tf(Bs[st][ks + tq][ncol]);
                    bf[nt][1] = f2tf(Bs[st][ks + tq + 4][ncol]);
                }
            }
#pragma unroll
            for (int mt = 0; mt < 4; mt++)
#pragma unroll
                for (int nt = 0; nt < 4; nt++)
                    mma_tf32(acc[mt][nt], af[mt], bf[nt]);
        }
        __syncthreads();
    }

    // ---- epilogue ----
#pragma unroll
    for (int mt = 0; mt < 4; mt++) {
        int row0 = m0 + warp_m * 64 + mt * 16 + g;
#pragma unroll
        for (int nt = 0; nt < 4; nt++) {
            int col = n0 + warp_n * 32 + nt * 8 + tq * 2;
#pragma unroll
            for (int half = 0; half < 2; half++) {
                int row = row0 + half * 8;
                if (row >= M) continue;
                float v0 = acc[mt][nt][half * 2 + 0] * alpha;
                float v1 = acc[mt][nt][half * 2 + 1] * alpha;
                if (col < N) {
                    float v = v0;
                    if (HAS_BIAS) v += bias[col];
                    if (HAS_RES)  v += Res[(size_t)row * ldc + col];
                    if (RELU)     v = fmaxf(v, 0.0f);
                    C[(size_t)row * ldc + col] = v;
                }
                if (col + 1 < N) {
                    float v = v1;
                    if (HAS_BIAS) v += bias[col + 1];
                    if (HAS_RES)  v += Res[(size_t)row * ldc + col + 1];
                    if (RELU)     v = fmaxf(v, 0.0f);
                    C[(size_t)row * ldc + col + 1] = v;
                }
            }
        }
    }
}

// ---------------- tgt init ----------------
__global__ void init_tgt(const float* __restrict__ qe) {
    size_t i = (size_t)blockIdx.x * 256 + threadIdx.x;
    int c = (int)(i & 255);
    int m = (int)(i >> 8);
    int q = m & 15;
    g_tgt[i] = qe[q * HID_ + c];
}

// ---------------- self attention ----------------
__global__ __launch_bounds__(256) void self_attn() {
    int bn = blockIdx.x;
    __shared__ float sq[NQ_][260];
    __shared__ float sk[NQ_][260];
    __shared__ float sa[HEADS_][NQ_][NQ_ + 1];
    int t = threadIdx.x;
    const float* base = g_qkv + (size_t)bn * NQ_ * 768;
    for (int i = t; i < NQ_ * HID_; i += 256) {
        int q = i >> 8, c = i & 255;
        sq[q][c] = base[q * 768 + c];
        sk[q][c] = base[q * 768 + 256 + c];
    }
    __syncthreads();
    const float scale = 0.17677669529663687f;
    for (int i = t; i < HEADS_ * NQ_ * NQ_; i += 256) {
        int h = i >> 8, q = (i >> 4) & 15, kk = i & 15;
        float acc = 0.0f;
#pragma unroll
        for (int d = 0; d < DH_; d++) acc += sq[q][h * DH_ + d] * sk[kk][h * DH_ + d];
        sa[h][q][kk] = acc * scale;
    }
    __syncthreads();
    if (t < HEADS_ * NQ_) {
        int h = t >> 4, q = t & 15;
        float m = -FLT_MAX;
#pragma unroll
        for (int kk = 0; kk < NQ_; kk++) m = fmaxf(m, sa[h][q][kk]);
        float s = 0.0f;
#pragma unroll
        for (int kk = 0; kk < NQ_; kk++) { float e = expf(sa[h][q][kk] - m); sa[h][q][kk] = e; s += e; }
        float inv = 1.0f / s;
#pragma unroll
        for (int kk = 0; kk < NQ_; kk++) sa[h][q][kk] *= inv;
    }
    __syncthreads();
    float* out = g_ctx + (size_t)bn * NQ_ * HID_;
    for (int i = t; i < NQ_ * HID_; i += 256) {
        int q = i >> 8, c = i & 255;
        int h = c >> 5;
        float acc = 0.0f;
#pragma unroll
        for (int kk = 0; kk < NQ_; kk++) acc += sa[h][q][kk] * base[kk * 768 + 512 + c];
        out[q * HID_ + c] = acc;
    }
}

// ---------------- cross-attn U = Q_h @ Wk_h ----------------
__global__ __launch_bounds__(256) void cross_u(const float* __restrict__ Wk) {
    int h = blockIdx.x, bn = blockIdx.y;
    int c = threadIdx.x;
    __shared__ float sq[NQ_][DH_];
    for (int i = threadIdx.x; i < NQ_ * DH_; i += 256) {
        int q = i >> 5, d = i & 31;
        sq[q][d] = g_qc[((size_t)bn * NQ_ + q) * HID_ + h * DH_ + d];
    }
    __syncthreads();
    float acc[NQ_] = {};
#pragma unroll 4
    for (int d = 0; d < DH_; d++) {
        float w = Wk[(size_t)(h * DH_ + d) * HID_ + c];
#pragma unroll
        for (int q = 0; q < NQ_; q++) acc[q] += sq[q][d] * w;
    }
    float* dst = g_u + ((size_t)bn * 128 + h * NQ_) * HID_ + c;
#pragma unroll
    for (int q = 0; q < NQ_; q++) dst[(size_t)q * HID_] = acc[q];
}

// ---------------- masked softmax over 225 keys (+zero the 15 pad cols) ----------------
__global__ __launch_bounds__(256) void softmax_cross() {
    int row = blockIdx.x * 8 + (threadIdx.x >> 5);
    int lane = threadIdx.x & 31;
    int bn = row >> 7;
    bool v = g_valid[bn] != 0;
    float* s = g_s + (size_t)row * SPAD_;
    float vals[8];
    float m = -FLT_MAX;
#pragma unroll
    for (int i = 0; i < 8; i++) {
        int k = lane + i * 32;
        bool active = (k < P2_) && (v || k == 0);
        float x = active ? s[k] : -FLT_MAX;
        vals[i] = active ? x : -INFINITY;
        m = fmaxf(m, vals[i]);
    }
#pragma unroll
    for (int o = 16; o; o >>= 1) m = fmaxf(m, __shfl_xor_sync(0xffffffffu, m, o));
    float sum = 0.0f;
#pragma unroll
    for (int i = 0; i < 8; i++) {
        int k = lane + i * 32;
        bool active = (k < P2_) && (v || k == 0);
        float e = active ? expf(vals[i] - m) : 0.0f;
        vals[i] = e;
        sum += e;
    }
#pragma unroll
    for (int o = 16; o; o >>= 1) sum += __shfl_xor_sync(0xffffffffu, sum, o);
    float inv = 1.0f / sum;
#pragma unroll
    for (int i = 0; i < 8; i++) {
        int k = lane + i * 32;
        if (k < P2_) s[k] = vals[i] * inv;
        else if (k < SPAD_) s[k] = 0.0f;       // zero pad for cp.async T GEMM
    }
}

// ---------------- cross-attn output: ctx = T @ Wv_h^T + bv ----------------
__global__ __launch_bounds__(512) void cross_o(const float* __restrict__ Wv,
                                               const float* __restrict__ bv) {
    int h = blockIdx.x, bn = blockIdx.y;
    __shared__ float ws[DH_][HID_ + 1];
    int t = threadIdx.x;
    for (int i = t; i < DH_ * HID_; i += 512) {
        int d = i >> 8, c = i & 255;
        ws[d][c] = Wv[(size_t)(h * DH_ + d) * HID_ + c];
    }
    __syncthreads();
    int q = t >> 5, d = t & 31;
    const float* trow = g_u + ((size_t)bn * 128 + h * NQ_ + q) * HID_;
    float acc = 0.0f;
#pragma unroll 4
    for (int c = 0; c < HID_; c += 4) {
        float4 tv = *reinterpret_cast<const float4*>(trow + c);
        acc += tv.x * ws[d][c] + tv.y * ws[d][c + 1] + tv.z * ws[d][c + 2] + tv.w * ws[d][c + 3];
    }
    g_ctx[((size_t)bn * NQ_ + q) * HID_ + h * DH_ + d] = acc + bv[h * DH_ + d];
}

// ---------------- layernorm ----------------
__global__ __launch_bounds__(256) void layernorm_k(const float* __restrict__ X,
                                                   const float* __restrict__ w,
                                                   const float* __restrict__ b,
                                                   float* __restrict__ Y) {
    int row = blockIdx.x * 8 + (threadIdx.x >> 5);
    int lane = threadIdx.x & 31;
    const float* x = X + (size_t)row * HID_;
    float v[8];
    float s = 0.0f;
#pragma unroll
    for (int i = 0; i < 8; i++) { v[i] = x[lane + i * 32]; s += v[i]; }
#pragma unroll
    for (int o = 16; o; o >>= 1) s += __shfl_xor_sync(0xffffffffu, s, o);
    float mu = s * (1.0f / 256.0f);
    float var = 0.0f;
#pragma unroll
    for (int i = 0; i < 8; i++) { float d = v[i] - mu; var += d * d; }
#pragma unroll
    for (int o = 16; o; o >>= 1) var += __shfl_xor_sync(0xffffffffu, var, o);
    var *= (1.0f / 256.0f);
    float r = rsqrtf(var + LN_EPS_);
    float* y = Y + (size_t)row * HID_;
#pragma unroll
    for (int i = 0; i < 8; i++) {
        int c = lane + i * 32;
        y[c] = (v[i] - mu) * r * w[c] + b[c];
    }
}

// ---------------- final head ----------------
__global__ __launch_bounds__(256) void final_out(const float* __restrict__ W,
                                                 const float* __restrict__ bias,
                                                 float* __restrict__ out) {
    int row = blockIdx.x * 8 + (threadIdx.x >> 5);
    int lane = threadIdx.x & 31;
    const float* x = g_tgt + (size_t)row * HID_;
    float acc[4] = {};
#pragma unroll
    for (int i = 0; i < 8; i++) {
        int c = lane + i * 32;
        float xv = x[c];
#pragma unroll
        for (int j = 0; j < 4; j++) acc[j] += xv * W[j * HID_ + c];
    }
#pragma unroll
    for (int j = 0; j < 4; j++)
#pragma unroll
        for (int o = 16; o; o >>= 1) acc[j] += __shfl_xor_sync(0xffffffffu, acc[j], o);
    if (lane < 4) out[(size_t)row * 4 + lane] = acc[lane] + bias[lane];
}

// ---------------- host ----------------
extern "C" void kernel_launch(void* const* d_in, const int* in_sizes, int n_in,
                              void* d_out, int out_size) {
    (void)in_sizes; (void)n_in; (void)out_size;
    const float* img         = (const float*)d_in[0];
    const float* kp          = (const float*)d_in[1];
    const unsigned char* msk = (const unsigned char*)d_in[2];
    const float* proj_w      = (const float*)d_in[3];
    const float* proj_b      = (const float*)d_in[4];
    const float* query_embed = (const float*)d_in[5];
    const float* self_qkv_w  = (const float*)d_in[6];
    const float* self_qkv_b  = (const float*)d_in[7];
    const float* self_out_w  = (const float*)d_in[8];
    const float* self_out_b  = (const float*)d_in[9];
    const float* cross_qkv_w = (const float*)d_in[10];
    const float* cross_qkv_b = (const float*)d_in[11];
    const float* cross_out_w = (const float*)d_in[12];
    const float* cross_out_b = (const float*)d_in[13];
    const float* ffn1_w      = (const float*)d_in[14];
    const float* ffn1_b      = (const float*)d_in[15];
    const float* ffn2_w      = (const float*)d_in[16];
    const float* ffn2_b      = (const float*)d_in[17];
    const float* ln1_w       = (const float*)d_in[18];
    const float* ln1_b       = (const float*)d_in[19];
    const float* ln2_w       = (const float*)d_in[20];
    const float* ln2_b       = (const float*)d_in[21];
    const float* ln3_w       = (const float*)d_in[22];
    const float* ln3_b       = (const float*)d_in[23];
    const float* out_w       = (const float*)d_in[24];
    const float* out_b       = (const float*)d_in[25];
    float* out = (float*)d_out;

    float *feat, *mem, *tgt, *y, *qkv, *ctx, *qc, *u, *s, *ffn;
    unsigned char* valid;
    cudaGetSymbolAddress((void**)&feat,  g_feat);
    cudaGetSymbolAddress((void**)&mem,   g_mem);
    cudaGetSymbolAddress((void**)&tgt,   g_tgt);
    cudaGetSymbolAddress((void**)&y,     g_y);
    cudaGetSymbolAddress((void**)&qkv,   g_qkv);
    cudaGetSymbolAddress((void**)&ctx,   g_ctx);
    cudaGetSymbolAddress((void**)&qc,    g_qc);
    cudaGetSymbolAddress((void**)&u,     g_u);
    cudaGetSymbolAddress((void**)&s,     g_s);
    cudaGetSymbolAddress((void**)&ffn,   g_ffn);
    cudaGetSymbolAddress((void**)&valid, g_valid);

    const float scale = 0.17677669529663687f;

    decode_mask<<<1, 512>>>(msk, valid);
    { dim3 g(WF_, HF_, B_); transpose_img<<<g, C_>>>(img); }
    { dim3 g(P2_, N_KP, B_); roi_gather<<<g, C_>>>(kp); }

    // mem = feat @ proj_w^T + proj_b
    gemm_tc<true, true, false, false><<<dim3(2, 900, 1), 256>>>(
        feat, proj_w, proj_b, nullptr, mem, MMEM_, HID_, C_, C_, C_, HID_, 0, 0, 0, 1.0f);

    init_tgt<<<MROWS_, 256>>>(query_embed);

    for (int l = 0; l < DEPTH_; l++) {
        const float* sW  = self_qkv_w  + (size_t)l * 3 * HID_ * HID_;
        const float* sB  = self_qkv_b  + (size_t)l * 3 * HID_;
        const float* soW = self_out_w  + (size_t)l * HID_ * HID_;
        const float* soB = self_out_b  + (size_t)l * HID_;
        const float* cW  = cross_qkv_w + (size_t)l * 3 * HID_ * HID_;
        const float* cB  = cross_qkv_b + (size_t)l * 3 * HID_;
        const float* coW = cross_out_w + (size_t)l * HID_ * HID_;
        const float* coB = cross_out_b + (size_t)l * HID_;
        const float* f1W = ffn1_w + (size_t)l * FFN_ * HID_;
        const float* f1B = ffn1_b + (size_t)l * FFN_;
        const float* f2W = ffn2_w + (size_t)l * HID_ * FFN_;
        const float* f2B = ffn2_b + (size_t)l * HID_;

        // --- self attention ---
        gemm_tc<true, true, false, false><<<dim3(6, 64, 1), 256>>>(
            tgt, sW, sB, nullptr, qkv, MROWS_, 3 * HID_, HID_, HID_, HID_, 3 * HID_, 0, 0, 0, 1.0f);
        self_attn<<<BN_, 256>>>();
        gemm_tc<true, true, true, false><<<dim3(2, 64, 1), 256>>>(
            ctx, soW, soB, tgt, y, MROWS_, HID_, HID_, HID_, HID_, HID_, 0, 0, 0, 1.0f);
        layernorm_k<<<MROWS_ / 8, 256>>>(y, ln1_w + l * HID_, ln1_b + l * HID_, tgt);

        // --- cross attention (factored K/V) ---
        gemm_tc<true, true, false, false><<<dim3(2, 64, 1), 256>>>(
            tgt, cW, cB, nullptr, qc, MROWS_, HID_, HID_, HID_, HID_, HID_, 0, 0, 0, 1.0f);
        { dim3 g(HEADS_, BN_); cross_u<<<g, 256>>>(cW + (size_t)HID_ * HID_); }
        // S = scale * U @ mem^T   (batched over bn)
        gemm_tc<true, false, false, false><<<dim3(2, 1, BN_), 256>>>(
            u, mem, nullptr, nullptr, s, 128, P2_, HID_, HID_, HID_, SPAD_,
            (long long)128 * HID_, (long long)P2_ * HID_, (long long)128 * SPAD_, scale);
        softmax_cross<<<(BN_ * 128) / 8, 256>>>();
        // T = A @ mem   (batched, NN)  -- K=225 padded to 240 with zeros in g_s
        gemm_tc<false, false, false, false><<<dim3(2, 1, BN_), 256>>>(
            s, mem, nullptr, nullptr, u, 128, HID_, P2_, SPAD_, HID_, HID_,
            (long long)128 * SPAD_, (long long)P2_ * HID_, (long long)128 * HID_, 1.0f);
        { dim3 g(HEADS_, BN_); cross_o<<<g, 512>>>(cW + (size_t)2 * HID_ * HID_, cB + 2 * HID_); }
        gemm_tc<true, true, true, false><<<dim3(2, 64, 1), 256>>>(
            ctx, coW, coB, tgt, y, MROWS_, HID_, HID_, HID_, HID_, HID_, 0, 0, 0, 1.0f);
        layernorm_k<<<MROWS_ / 8, 256>>>(y, ln2_w + l * HID_, ln2_b + l * HID_, tgt);

        // --- FFN ---
        gemm_tc<true, true, false, true><<<dim3(8, 64, 1), 256>>>(
            tgt, f1W, f1B, nullptr, ffn, MROWS_, FFN_, HID_, HID_, HID_, FFN_, 0, 0, 0, 1.0f);
        gemm_tc<true, true, true, false><<<dim3(2, 64, 1), 256>>>(
            ffn, f2W, f2B, tgt, y, MROWS_, HID_, FFN_, FFN_, FFN_, HID_, 0, 0, 0, 1.0f);
        layernorm_k<<<MROWS_ / 8, 256>>>(y, ln3_w + l * HID_, ln3_b + l * HID_, tgt);
    }

    final_out<<<MROWS_ / 8, 256>>>(out_w, out_b, out);
}